// round 16
// baseline (speedup 1.0000x reference)
#include <cuda_runtime.h>
#include <cuda_bf16.h>
#include <cstdint>

// Problem: B=8, H=128, W=128, C=64, stride 2x2 max-unpool scatter-add.
// inputs  : [8,128,128,64] float32  -> 8,388,608 elements
// indices : [8,128,128,64] int32/int64 -> per-batch flat index into 256*256*64
// output  : [8,256,256,64] float32  -> 33,554,432 elements
static constexpr long long PER_BATCH_OUT = 256LL * 256 * 64;      // 2^22 (16MB)
static constexpr int NUM_BATCH = 8;
static constexpr int NSTAGE    = NUM_BATCH + 1;   // stage s: zero b=s, scatter b=s-1

static constexpr int BLOCK = 256;
// Zero blocks FIRST (low blockIdx -> CTA-FIFO priority, so semaphores post
// promptly): 1024 blocks x 4 float4/thread = 16MB. Scatter: 1024 blocks x
// 4 elems/thread = 1,048,576 elems.
static constexpr int ZBLK = 1024;
static constexpr int SBLK = 1024;
static constexpr int GRID = ZBLK + SBLK;   // 2048

// Probe flags + per-batch zero-completion semaphores (reset by init kernel).
__device__ int g_swap;                 // 1 if d_in[0] is the indices buffer
__device__ int g_is64;                 // 1 if indices are int64
__device__ int g_zdone[NUM_BATCH];     // count of completed zero blocks per batch

// ---------------------------------------------------------------------------
// Init: probe index layout + reset semaphores. Plain launch (no PDL): fully
// completes before stage 0 starts, and replay N's last stage completes before
// replay N+1's init (stream order), so resets never race live semaphores.
// ---------------------------------------------------------------------------
__global__ void init_kernel(const int* __restrict__ a, const int* __restrict__ b) {
    int k = threadIdx.x;
    // Indices are small non-negative ints (< 2^22); normal float bits read as
    // int32 are ~1e9 or negative. int64 < 2^22 has all odd 32-bit words == 0.
    bool ok_a = (a[k] >= 0 && a[k] < (int)PER_BATCH_OUT);
    bool ok_b = (b[k] >= 0 && b[k] < (int)PER_BATCH_OUT);
    int ca = __syncthreads_count(ok_a);
    int cb = __syncthreads_count(ok_b);
    int swap = (ca > cb) ? 1 : 0;
    const int* idx = swap ? a : b;
    int nz = __syncthreads_count(idx[2 * k + 1] != 0);
    if (k == 0) { g_swap = swap; g_is64 = (nz == 0) ? 1 : 0; }
    if (k < NUM_BATCH) g_zdone[k] = 0;
}

// ---------------------------------------------------------------------------
// Stage kernel. NO grid-wide dependency sync: ordering zero(b) -> scatter(b)
// is enforced by the g_zdone[b] semaphore, so scatter(b)'s atomics start as
// soon as batch b is zeroed — WITHOUT waiting for scatter(b-1)'s atomic
// drain (false dependency that serialized every previous version). PDL
// triggers let adjacent stages co-schedule; CTA-FIFO order (zero blocks
// first, grids drained in launch order) guarantees spinners' producers are
// always resident or ahead of them -> no deadlock.
// L2 staging preserved: zero(b) dirties the 16MB slice in L2; REDs do
// L2-resident RMW; __ldcs keeps the streams from evicting those lines.
// ---------------------------------------------------------------------------
__global__ void __launch_bounds__(BLOCK) stage_kernel(
        const void* __restrict__ p0,
        const void* __restrict__ p1,
        float*      __restrict__ out,
        int stage) {

    cudaTriggerProgrammaticLaunchCompletion();

    if (blockIdx.x < ZBLK) {
        // ---- zero role: batch = stage, 4x STG.128/thread ----
        if (stage >= NUM_BATCH) return;
        float4* dst = reinterpret_cast<float4*>(out + ((long long)stage << 22));
        const long long t = (long long)blockIdx.x * BLOCK + threadIdx.x; // [0,262144)
        const float4 zz = make_float4(0.f, 0.f, 0.f, 0.f);
        #pragma unroll
        for (int r = 0; r < 4; r++)
            dst[t + (long long)r * 262144LL] = zz;
        // Release: make this block's stores visible, then post the semaphore.
        __threadfence();
        __syncthreads();
        if (threadIdx.x == 0)
            atomicAdd(&g_zdone[stage], 1);
        return;
    }

    // ---- scatter role: batch = stage - 1, 4 elems/thread ----
    if (stage == 0) return;

    const long long b  = stage - 1;
    const long long u  = (long long)(blockIdx.x - ZBLK) * BLOCK + threadIdx.x;
    const long long tg = (b << 18) + u;               // global 4-elem group id
    const long long i  = tg << 2;

    // init_kernel completed before stage 0 started (plain launch), and every
    // later stage transitively started after stage 0 began -> flags valid.
    const int swap = g_swap;
    const int is64 = g_is64;
    const float* in  = (const float*)(swap ? p1 : p0);
    const void*  idx = swap ? p0 : p1;

    // Front-batched independent loads — issue BEFORE the spin so their
    // latency hides under the wait.
    const float4 v = __ldcs(reinterpret_cast<const float4*>(in + i));
    long long j0, j1, j2, j3;
    if (is64) {
        const longlong2 a0 = __ldcs(reinterpret_cast<const longlong2*>(idx) + tg * 2 + 0);
        const longlong2 a1 = __ldcs(reinterpret_cast<const longlong2*>(idx) + tg * 2 + 1);
        j0 = a0.x; j1 = a0.y; j2 = a1.x; j3 = a1.y;
    } else {
        const int4 a = __ldcs(reinterpret_cast<const int4*>(idx) + tg);
        j0 = a.x; j1 = a.y; j2 = a.z; j3 = a.w;
    }

    // Acquire: wait for all ZBLK zero blocks of batch b to have posted.
    if (threadIdx.x == 0) {
        while (atomicAdd(&g_zdone[b], 0) < ZBLK)
            __nanosleep(64);
    }
    __syncthreads();
    __threadfence();

    float* ob = out + (b << 22);   // batch base (all 4 elems same batch)
    if ((unsigned long long)j0 < (unsigned long long)PER_BATCH_OUT) atomicAdd(ob + j0, v.x);
    if ((unsigned long long)j1 < (unsigned long long)PER_BATCH_OUT) atomicAdd(ob + j1, v.y);
    if ((unsigned long long)j2 < (unsigned long long)PER_BATCH_OUT) atomicAdd(ob + j2, v.z);
    if ((unsigned long long)j3 < (unsigned long long)PER_BATCH_OUT) atomicAdd(ob + j3, v.w);
}

extern "C" void kernel_launch(void* const* d_in, const int* in_sizes, int n_in,
                              void* d_out, int out_size) {
    const void* p0 = d_in[0];
    const void* p1 = d_in[1];
    float* out = (float*)d_out;

    // Init: probe + semaphore reset (plain launch — gates stage 0).
    init_kernel<<<1, 256>>>((const int*)p0, (const int*)p1);

    // PDL-allowed stage launches: each triggers at entry, so stages
    // co-schedule and the per-batch semaphores provide the only ordering.
    cudaLaunchAttribute attr[1];
    attr[0].id = cudaLaunchAttributeProgrammaticStreamSerialization;
    attr[0].val.programmaticStreamSerializationAllowed = 1;

    cudaLaunchConfig_t cfg = {};
    cfg.gridDim  = dim3(GRID, 1, 1);
    cfg.blockDim = dim3(BLOCK, 1, 1);
    cfg.stream = 0;
    cfg.attrs = attr;
    cfg.numAttrs = 1;

    // Stage 0: zero batch 0. Stages 1..7: zero b + scatter b-1.
    // Stage 8: scatter batch 7 only.
    for (int stage = 0; stage < NSTAGE; stage++) {
        cudaLaunchKernelEx(&cfg, stage_kernel, p0, p1, out, stage);
    }
}

// round 17
// speedup vs baseline: 1.2333x; 1.2333x over previous
#include <cuda_runtime.h>
#include <cuda_bf16.h>
#include <cstdint>

// Problem: B=8, H=128, W=128, C=64, stride 2x2 max-unpool scatter-add.
// inputs  : [8,128,128,64] float32  -> 8,388,608 elements
// indices : [8,128,128,64] int32/int64 -> per-batch flat index into 256*256*64
// output  : [8,256,256,64] float32  -> 33,554,432 elements
static constexpr long long PER_BATCH_OUT = 256LL * 256 * 64;      // 2^22 (16MB)
static constexpr unsigned  PBO_U         = 1u << 22;
static constexpr int NUM_BATCH = 8;
static constexpr int NSTAGE    = NUM_BATCH + 1;   // stage s: zero b=s, scatter b=s-1

static constexpr int BLOCK = 256;
static constexpr int GRID  = 1024;   // uniform blocks: each zeroes AND scatters

// Runtime-detected layout flags (set by the probe in stage 0).
__device__ int g_swap;   // 1 if d_in[0] is the indices buffer
__device__ int g_is64;   // 1 if indices are int64

// ---------------------------------------------------------------------------
// Stage kernel, uniform fused roles + PDL (the 84us champion shape).
// Every thread: 3x16B scatter loads for batch s-1 (pre-sync, hidden under the
// previous stage's atomic drain) + 4x STG.128 zeroing batch s (independent,
// fire-and-forget) + 4 REDs post-sync. Zero(b) one launch before scatter(b)
// keeps each 16MB atomic RMW working set L2-resident (no DRAM RMW); __ldcs
// keeps the streams from evicting those lines. Atomic addressing uses 32-bit
// offsets (indices < 2^22) to trim the IMAD chain per element.
// ---------------------------------------------------------------------------
__global__ void __launch_bounds__(BLOCK) stage_kernel(
        const void* __restrict__ p0,
        const void* __restrict__ p1,
        float*      __restrict__ out,
        int stage) {

    cudaTriggerProgrammaticLaunchCompletion();

    const long long t = (long long)blockIdx.x * BLOCK + threadIdx.x;  // [0, 262144)

    // ---- scatter loads (batch s-1), issued FIRST: longest dependency chain.
    unsigned j0 = ~0u, j1 = ~0u, j2 = ~0u, j3 = ~0u;
    float4 v = make_float4(0.f, 0.f, 0.f, 0.f);
    int swap_s = 0, is64_s = 0;
    const long long b = (long long)stage - 1;
    if (stage > 0) {
        swap_s = __ldcg(&g_swap);
        is64_s = __ldcg(&g_is64);
        const float* in  = (const float*)(swap_s ? p1 : p0);
        const void*  idx = swap_s ? p0 : p1;
        const long long tg = (b << 18) + t;     // global 4-elem group id
        const long long i  = tg << 2;
        v = __ldcs(reinterpret_cast<const float4*>(in + i));
        if (is64_s) {
            const longlong2 a0 = __ldcs(reinterpret_cast<const longlong2*>(idx) + tg * 2 + 0);
            const longlong2 a1 = __ldcs(reinterpret_cast<const longlong2*>(idx) + tg * 2 + 1);
            j0 = (unsigned)a0.x; j1 = (unsigned)a0.y;
            j2 = (unsigned)a1.x; j3 = (unsigned)a1.y;
            // Preserve out-of-range detection for 64-bit values.
            if ((unsigned long long)a0.x >= (unsigned long long)PER_BATCH_OUT) j0 = ~0u;
            if ((unsigned long long)a0.y >= (unsigned long long)PER_BATCH_OUT) j1 = ~0u;
            if ((unsigned long long)a1.x >= (unsigned long long)PER_BATCH_OUT) j2 = ~0u;
            if ((unsigned long long)a1.y >= (unsigned long long)PER_BATCH_OUT) j3 = ~0u;
        } else {
            const int4 a = __ldcs(reinterpret_cast<const int4*>(idx) + tg);
            j0 = (unsigned)a.x; j1 = (unsigned)a.y;
            j2 = (unsigned)a.z; j3 = (unsigned)a.w;
        }
    }

    // ---- zero stores (batch s): independent, fire-and-forget.
    if (stage < NUM_BATCH) {
        float4* dst = reinterpret_cast<float4*>(out + ((long long)stage << 22));
        const float4 zz = make_float4(0.f, 0.f, 0.f, 0.f);
        #pragma unroll
        for (int r = 0; r < 4; r++)
            dst[t + (long long)r * 262144LL] = zz;
    }

    // ---- probe (stage 0, block 0): detect index buffer + width.
    // Indices are small non-negative ints (< 2^22); normal float bits read as
    // int32 are ~1e9 or negative. int64 < 2^22 has all odd 32-bit words == 0.
    if (stage == 0) {
        if (blockIdx.x == 0) {
            const int* a  = (const int*)p0;
            const int* bb = (const int*)p1;
            int k = threadIdx.x;
            bool ok_a = (a[k]  >= 0 && a[k]  < (int)PER_BATCH_OUT);
            bool ok_b = (bb[k] >= 0 && bb[k] < (int)PER_BATCH_OUT);
            int ca = __syncthreads_count(ok_a);
            int cb = __syncthreads_count(ok_b);
            int swap = (ca > cb) ? 1 : 0;
            const int* idx = swap ? a : bb;
            int nz = __syncthreads_count(idx[2 * k + 1] != 0);
            if (k == 0) { g_swap = swap; g_is64 = (nz == 0) ? 1 : 0; }
        }
        return;
    }

    // ---- wait for previous grid (zero of batch b + probe).
    cudaGridDependencySynchronize();

    // Re-check flags; reload if the speculation was wrong (at most once ever,
    // while stage 0's probe was still in flight; deterministic on replays).
    {
        int swap_c = __ldcg(&g_swap);
        int is64_c = __ldcg(&g_is64);
        if (swap_c != swap_s || is64_c != is64_s) {
            const float* in2  = (const float*)(swap_c ? p1 : p0);
            const void*  idx2 = swap_c ? p0 : p1;
            const long long tg = (b << 18) + t;
            const long long i  = tg << 2;
            v = __ldcs(reinterpret_cast<const float4*>(in2 + i));
            if (is64_c) {
                const longlong2 a0 = __ldcs(reinterpret_cast<const longlong2*>(idx2) + tg * 2 + 0);
                const longlong2 a1 = __ldcs(reinterpret_cast<const longlong2*>(idx2) + tg * 2 + 1);
                j0 = ((unsigned long long)a0.x < (unsigned long long)PER_BATCH_OUT) ? (unsigned)a0.x : ~0u;
                j1 = ((unsigned long long)a0.y < (unsigned long long)PER_BATCH_OUT) ? (unsigned)a0.y : ~0u;
                j2 = ((unsigned long long)a1.x < (unsigned long long)PER_BATCH_OUT) ? (unsigned)a1.x : ~0u;
                j3 = ((unsigned long long)a1.y < (unsigned long long)PER_BATCH_OUT) ? (unsigned)a1.y : ~0u;
            } else {
                const int4 a = __ldcs(reinterpret_cast<const int4*>(idx2) + tg);
                j0 = (unsigned)a.x; j1 = (unsigned)a.y;
                j2 = (unsigned)a.z; j3 = (unsigned)a.w;
            }
        }
    }

    // ---- scatter atomics (REDG; 32-bit offsets, bounds-guarded).
    float* ob = out + (b << 22);
    if (j0 < PBO_U) atomicAdd(ob + j0, v.x);
    if (j1 < PBO_U) atomicAdd(ob + j1, v.y);
    if (j2 < PBO_U) atomicAdd(ob + j2, v.z);
    if (j3 < PBO_U) atomicAdd(ob + j3, v.w);
}

extern "C" void kernel_launch(void* const* d_in, const int* in_sizes, int n_in,
                              void* d_out, int out_size) {
    const void* p0 = d_in[0];
    const void* p1 = d_in[1];
    float* out = (float*)d_out;

    cudaLaunchAttribute attr[1];
    attr[0].id = cudaLaunchAttributeProgrammaticStreamSerialization;
    attr[0].val.programmaticStreamSerializationAllowed = 1;

    cudaLaunchConfig_t cfg = {};
    cfg.gridDim  = dim3(GRID, 1, 1);
    cfg.blockDim = dim3(BLOCK, 1, 1);
    cfg.stream = 0;
    cfg.attrs = attr;
    cfg.numAttrs = 1;

    // Stage 0: zero batch 0 + probe. Stages 1..7: zero b + scatter b-1.
    // Stage 8: scatter batch 7 only.
    for (int stage = 0; stage < NSTAGE; stage++) {
        cudaLaunchKernelEx(&cfg, stage_kernel, p0, p1, out, stage);
    }
}